// round 12
// baseline (speedup 1.0000x reference)
#include <cuda_runtime.h>
#include <cuda_bf16.h>
#include <cstdint>
#include <math.h>

typedef __nv_bfloat16 bf16;

#define B_   8
#define N_   1024
#define D_   384
#define H_   8
#define HD_  48
#define HID_ 1536
#define ROWS 8192
#define QSCALE 0.14433756729740643f
#define LOG2E 1.4426950408889634f

// ------------------- static scratch (no allocation allowed) -----------------
__device__ bf16  g_hb  [ROWS * D_];
__device__ bf16  g_act [ROWS * HID_];
__device__ bf16  g_q   [B_ * H_ * N_ * HD_];
__device__ bf16  g_k   [B_ * H_ * N_ * HD_];
__device__ bf16  g_vT  [B_ * H_ * 64 * N_];   // zero-init; pad rows 48..63 never written
__device__ bf16  g_E   [(size_t)B_ * N_ * N_ * H_];   // exp(premixed logits), (b,i,j,h)
__device__ float g_Zp  [B_ * N_ * H_ * 64];           // Z partials (jb x warp-col)
__device__ bf16  g_o   [ROWS * D_];
__device__ float g_x1  [ROWS * D_];
__device__ bf16  g_wqkv [3 * D_ * D_];
__device__ bf16  g_wproj[D_ * D_];
__device__ bf16  g_wfc1 [HID_ * D_];
__device__ bf16  g_wfc2 [D_ * HID_];

// ------------------- fused fp32 -> bf16 convert for all 4 weights -----------
__global__ void cvt_all_kernel(const float* w0, bf16* o0, const float* w1, bf16* o1,
                               const float* w2, bf16* o2, const float* w3, bf16* o3)
{
    int i = blockIdx.x * 256 + threadIdx.x;            // float4 index
    const float* src;
    bf16* dst;
    int base;
    if (i < 110592)       { src = w0; dst = o0; base = i; }
    else if (i < 147456)  { src = w1; dst = o1; base = i - 110592; }
    else if (i < 294912)  { src = w2; dst = o2; base = i - 147456; }
    else if (i < 442368)  { src = w3; dst = o3; base = i - 294912; }
    else return;
    float4 v = reinterpret_cast<const float4*>(src)[base];
    reinterpret_cast<__nv_bfloat162*>(dst)[2 * base]     = __floats2bfloat162_rn(v.x, v.y);
    reinterpret_cast<__nv_bfloat162*>(dst)[2 * base + 1] = __floats2bfloat162_rn(v.z, v.w);
}

// ------------------- LayerNorm fp32 -> bf16 ---------------------------------
__global__ void ln_kernel(const float* __restrict__ x, const float* __restrict__ gw,
                          const float* __restrict__ bw, bf16* __restrict__ out)
{
    int row = blockIdx.x;
    int t   = threadIdx.x;
    const float* xr = x + (size_t)row * D_;
    float v0 = xr[t], v1 = xr[t + 128], v2 = xr[t + 256];
    float s  = v0 + v1 + v2;
    float ss = v0 * v0 + v1 * v1 + v2 * v2;
    for (int o = 16; o > 0; o >>= 1) {
        s  += __shfl_xor_sync(0xffffffffu, s,  o);
        ss += __shfl_xor_sync(0xffffffffu, ss, o);
    }
    __shared__ float rs[4];
    __shared__ float rq[4];
    if ((t & 31) == 0) { rs[t >> 5] = s; rq[t >> 5] = ss; }
    __syncthreads();
    s  = rs[0] + rs[1] + rs[2] + rs[3];
    ss = rq[0] + rq[1] + rq[2] + rq[3];
    float mean = s * (1.0f / 384.0f);
    float var  = ss * (1.0f / 384.0f) - mean * mean;
    float rstd = rsqrtf(var + 1e-5f);
    bf16* orow = out + (size_t)row * D_;
    orow[t]       = __float2bfloat16((v0 - mean) * rstd * gw[t]       + bw[t]);
    orow[t + 128] = __float2bfloat16((v1 - mean) * rstd * gw[t + 128] + bw[t + 128]);
    orow[t + 256] = __float2bfloat16((v2 - mean) * rstd * gw[t + 256] + bw[t + 256]);
}

// ------------------- PTX helpers --------------------------------------------
__device__ __forceinline__ void mma16816(float* c, const uint32_t* a, const uint32_t* b)
{
    asm volatile(
        "mma.sync.aligned.m16n8k16.row.col.f32.bf16.bf16.f32 "
        "{%0,%1,%2,%3}, {%4,%5,%6,%7}, {%8,%9}, {%0,%1,%2,%3};\n"
        : "+f"(c[0]), "+f"(c[1]), "+f"(c[2]), "+f"(c[3])
        : "r"(a[0]), "r"(a[1]), "r"(a[2]), "r"(a[3]), "r"(b[0]), "r"(b[1]));
}

__device__ __forceinline__ void cp_async16(uint32_t dst, const void* src)
{
    asm volatile("cp.async.cg.shared.global [%0], [%1], 16;\n" :: "r"(dst), "l"(src));
}
__device__ __forceinline__ void cp_commit()
{
    asm volatile("cp.async.commit_group;\n");
}
__device__ __forceinline__ void cp_wait0()
{
    asm volatile("cp.async.wait_group 0;\n" ::: "memory");
}
__device__ __forceinline__ void cp_wait1()
{
    asm volatile("cp.async.wait_group 1;\n" ::: "memory");
}

__device__ __forceinline__ float ex2f(float x)
{
    float y;
    asm("ex2.approx.f32 %0, %1;" : "=f"(y) : "f"(x));
    return y;
}
__device__ __forceinline__ float rcpf(float x)
{
    float y;
    asm("rcp.approx.f32 %0, %1;" : "=f"(y) : "f"(x));
    return y;
}

__device__ __forceinline__ uint32_t bf2_raw(__nv_bfloat162 v)
{
    return *reinterpret_cast<uint32_t*>(&v);
}
__device__ __forceinline__ __nv_bfloat162 raw_bf2(uint32_t v)
{
    return *reinterpret_cast<__nv_bfloat162*>(&v);
}

// ------------------- tensor-core GEMM  C = A @ B^T --------------------------
// 3-stage cp.async pipeline, 256 threads. MODE 0: qkv scatter; MODE 3: GELU;
// MODE 4: bias + residual + layerscale.
template<int BM, int BN, int MODE>
__global__ void __launch_bounds__(256)
gemm_kernel(const bf16* __restrict__ A, const bf16* __restrict__ Bw,
            int M, int N, int K, int lda, int ldb,
            const float* __restrict__ bias, const float* __restrict__ resid,
            const float* __restrict__ gamma, float* __restrict__ fout,
            bf16* __restrict__ bout, bf16* __restrict__ qo,
            bf16* __restrict__ ko, bf16* __restrict__ vo)
{
    constexpr int WM_CNT = BM / 32;
    constexpr int WN_TILE = BN * WM_CNT / 8;
    constexpr int NT = WN_TILE / 8;
    constexpr int A_STAGE = BM * 24;
    constexpr int B_STAGE = BN * 24;

    __shared__ bf16 As[3][BM][24];
    __shared__ bf16 Bs[3][BN][24];

    const int tid = threadIdx.x;
    const int w = tid >> 5;
    const int l = tid & 31;
    const int g = l >> 2;
    const int t = l & 3;
    const int wm = (w % WM_CNT) * 32;
    const int wn = (w / WM_CNT) * WN_TILE;
    const int m0 = blockIdx.y * BM;
    const int n0 = blockIdx.x * BN;

    const bf16* Ap = A;
    const bf16* Bp = Bw;

    const int arow = tid >> 1;
    const int acg  = (tid & 1) * 8;
    const int brow = tid >> 1;
    const int bcg  = (tid & 1) * 8;
    const bool doA = (tid < BM * 2);
    const bool doB = (tid < BN * 2);

    const bf16* aSrc = Ap + (size_t)(m0 + (doA ? arow : 0)) * lda + acg;
    const bf16* bSrc = Bp + (size_t)(n0 + (doB ? brow : 0)) * ldb + bcg;
    const uint32_t aDst0 = (uint32_t)__cvta_generic_to_shared(&As[0][doA ? arow : 0][acg]);
    const uint32_t bDst0 = (uint32_t)__cvta_generic_to_shared(&Bs[0][doB ? brow : 0][bcg]);

    float acc[2][NT][4];
    for (int mi = 0; mi < 2; mi++)
        for (int ni = 0; ni < NT; ni++)
            for (int e = 0; e < 4; e++)
                acc[mi][ni][e] = 0.0f;

    const int niter = K >> 4;

    if (doA) cp_async16(aDst0, aSrc);
    if (doB) cp_async16(bDst0, bSrc);
    cp_commit();
    if (niter > 1) {
        if (doA) cp_async16(aDst0 + A_STAGE * 2, aSrc + 16);
        if (doB) cp_async16(bDst0 + B_STAGE * 2, bSrc + 16);
    }
    cp_commit();

    int buf = 0;
    for (int it = 0; it < niter; it++) {
        cp_wait1();
        __syncthreads();
        {
            int pf = buf + 2; if (pf >= 3) pf -= 3;
            if (it + 2 < niter) {
                int kn = (it + 2) << 4;
                if (doA) cp_async16(aDst0 + (uint32_t)pf * (A_STAGE * 2), aSrc + kn);
                if (doB) cp_async16(bDst0 + (uint32_t)pf * (B_STAGE * 2), bSrc + kn);
            }
            cp_commit();
        }

        const bf16 (*Ab)[24] = As[buf];
        const bf16 (*Bb)[24] = Bs[buf];

        uint32_t af[2][4];
        for (int mi = 0; mi < 2; mi++) {
            int r = wm + mi * 16 + g;
            af[mi][0] = *reinterpret_cast<const uint32_t*>(&Ab[r][2 * t]);
            af[mi][1] = *reinterpret_cast<const uint32_t*>(&Ab[r + 8][2 * t]);
            af[mi][2] = *reinterpret_cast<const uint32_t*>(&Ab[r][2 * t + 8]);
            af[mi][3] = *reinterpret_cast<const uint32_t*>(&Ab[r + 8][2 * t + 8]);
        }
        uint32_t bfm[NT][2];
        for (int ni = 0; ni < NT; ni++) {
            int c = wn + ni * 8 + g;
            bfm[ni][0] = *reinterpret_cast<const uint32_t*>(&Bb[c][2 * t]);
            bfm[ni][1] = *reinterpret_cast<const uint32_t*>(&Bb[c][2 * t + 8]);
        }
        for (int mi = 0; mi < 2; mi++)
            for (int ni = 0; ni < NT; ni++)
                mma16816(acc[mi][ni], af[mi], bfm[ni]);

        buf++; if (buf == 3) buf = 0;
    }

    for (int mi = 0; mi < 2; mi++) {
        for (int ni = 0; ni < NT; ni++) {
            for (int hh = 0; hh < 2; hh++) {
                int row = m0 + wm + mi * 16 + g + hh * 8;
                int col = n0 + wn + ni * 8 + 2 * t;
                float v0 = acc[mi][ni][hh * 2 + 0];
                float v1 = acc[mi][ni][hh * 2 + 1];
                if (MODE == 0) {
                    int t3 = col / D_;
                    int r  = col - t3 * D_;
                    int hd = r / HD_;
                    int dd = r - hd * HD_;
                    int bb = row >> 10;
                    int ii = row & 1023;
                    size_t qk = ((size_t)(bb * H_ + hd) * N_ + ii) * HD_ + dd;
                    if (t3 == 0) {
                        __nv_bfloat162 p = __floats2bfloat162_rn(v0 * QSCALE, v1 * QSCALE);
                        *reinterpret_cast<__nv_bfloat162*>(&qo[qk]) = p;
                    } else if (t3 == 1) {
                        __nv_bfloat162 p = __floats2bfloat162_rn(v0, v1);
                        *reinterpret_cast<__nv_bfloat162*>(&ko[qk]) = p;
                    } else {
                        size_t vb = ((size_t)(bb * H_ + hd) * 64 + dd) * N_ + ii;
                        vo[vb]      = __float2bfloat16(v0);
                        vo[vb + N_] = __float2bfloat16(v1);
                    }
                } else if (MODE == 3) {
                    // GELU via sigmoid approximation: x * sigmoid(1.702 x)
                    float a0 = v0 + bias[col];
                    float a1 = v1 + bias[col + 1];
                    float s0 = rcpf(1.0f + ex2f(-1.702f * LOG2E * a0));
                    float s1 = rcpf(1.0f + ex2f(-1.702f * LOG2E * a1));
                    a0 *= s0;
                    a1 *= s1;
                    __nv_bfloat162 p = __floats2bfloat162_rn(a0, a1);
                    *reinterpret_cast<__nv_bfloat162*>(&bout[(size_t)row * N + col]) = p;
                } else {
                    float2 rr = *reinterpret_cast<const float2*>(&resid[(size_t)row * N + col]);
                    float2 o2;
                    o2.x = rr.x + gamma[col]     * (v0 + bias[col]);
                    o2.y = rr.y + gamma[col + 1] * (v1 + bias[col + 1]);
                    *reinterpret_cast<float2*>(&fout[(size_t)row * N + col]) = o2;
                }
            }
        }
    }
}

// ------------------- K1: QK^T (8 heads, bf16x2 regs) + packed premix + exp --
// grid (32 jb, 16 ib, 8 b); 256 threads; tile 64(i) x 32(j); static smem ~22KB.
__global__ void __launch_bounds__(256, 2)
score_mix_kernel(const bf16* __restrict__ q, const bf16* __restrict__ k,
                 const float* __restrict__ wl, const float* __restrict__ bl,
                 bf16* __restrict__ E, float* __restrict__ Zp)
{
    __shared__ bf16 Qs[2][64][56];
    __shared__ bf16 Ks[2][32][56];
    __shared__ __nv_bfloat162 wls2[64];
    __shared__ __nv_bfloat162 bls2[8];

    const int tid = threadIdx.x;
    const int jb  = blockIdx.x;           // 0..31
    const int j0  = jb * 32;
    const int i0  = blockIdx.y * 64;
    const int b   = blockIdx.z;

    if (tid < 64) wls2[tid] = __float2bfloat162_rn(wl[tid] * LOG2E);
    if (tid < 8)  bls2[tid] = __float2bfloat162_rn(bl[tid] * LOG2E);

    const int w = tid >> 5, l = tid & 31, gq = l >> 2, t = l & 3;
    const int wm = (w & 3) * 16;          // rows 0..63 in 4 warp-rows
    const int wc = w >> 2;                // 0..1
    const int wn = wc * 16;               // cols 0..31 in 2 warp-cols

    auto loadQK = [&](int h, int buf) {
        const bf16* qsrc = q + ((size_t)(b * H_ + h) * N_ + i0) * HD_;
        const bf16* ksrc = k + ((size_t)(b * H_ + h) * N_ + j0) * HD_;
        for (int idx = tid; idx < 576; idx += 256) {
            if (idx < 384) {
                int r = idx / 6, c = (idx - r * 6) * 8;
                cp_async16((uint32_t)__cvta_generic_to_shared(&Qs[buf][r][c]),
                           qsrc + (size_t)r * HD_ + c);
            } else {
                int k2 = idx - 384;
                int r = k2 / 6, c = (k2 - r * 6) * 8;
                cp_async16((uint32_t)__cvta_generic_to_shared(&Ks[buf][r][c]),
                           ksrc + (size_t)r * HD_ + c);
            }
        }
    };

    __nv_bfloat162 hacc[8][4];           // [head][pg], pg = nf*2+hh, pair (col,col+1)

    loadQK(0, 0);
    cp_commit();

#pragma unroll
    for (int h = 0; h < 8; h++) {
        cp_wait0();
        __syncthreads();
        if (h + 1 < 8) loadQK(h + 1, (h + 1) & 1);
        cp_commit();

        const bf16 (*Qb)[56] = Qs[h & 1];
        const bf16 (*Kb)[56] = Ks[h & 1];

        float acc[2][4];
#pragma unroll
        for (int nf = 0; nf < 2; nf++)
#pragma unroll
            for (int e = 0; e < 4; e++) acc[nf][e] = 0.0f;

#pragma unroll
        for (int k0 = 0; k0 < 48; k0 += 16) {
            uint32_t a[4];
            a[0] = *reinterpret_cast<const uint32_t*>(&Qb[wm + gq][k0 + 2 * t]);
            a[1] = *reinterpret_cast<const uint32_t*>(&Qb[wm + gq + 8][k0 + 2 * t]);
            a[2] = *reinterpret_cast<const uint32_t*>(&Qb[wm + gq][k0 + 2 * t + 8]);
            a[3] = *reinterpret_cast<const uint32_t*>(&Qb[wm + gq + 8][k0 + 2 * t + 8]);
#pragma unroll
            for (int nf = 0; nf < 2; nf++) {
                uint32_t bb[2];
                bb[0] = *reinterpret_cast<const uint32_t*>(&Kb[wn + nf * 8 + gq][k0 + 2 * t]);
                bb[1] = *reinterpret_cast<const uint32_t*>(&Kb[wn + nf * 8 + gq][k0 + 2 * t + 8]);
                mma16816(acc[nf], a, bb);
            }
        }
#pragma unroll
        for (int nf = 0; nf < 2; nf++)
#pragma unroll
            for (int hh = 0; hh < 2; hh++)
                hacc[h][nf * 2 + hh] =
                    __floats2bfloat162_rn(acc[nf][hh * 2 + 0], acc[nf][hh * 2 + 1]);
    }

    // ---- packed premix (HFMA2) + exp2 (h2exp2) + Z, all in registers -------
    __nv_bfloat162 e[4][8];              // [pg][g]
    float zacc[2][8];
#pragma unroll
    for (int hh = 0; hh < 2; hh++)
#pragma unroll
        for (int gg = 0; gg < 8; gg++) zacc[hh][gg] = 0.0f;

#pragma unroll
    for (int gg = 0; gg < 8; gg++) {
        __nv_bfloat162 w8[8];
#pragma unroll
        for (int h = 0; h < 8; h++) w8[h] = wls2[gg * 8 + h];
        const __nv_bfloat162 bb2 = bls2[gg];
#pragma unroll
        for (int pg = 0; pg < 4; pg++) {
            __nv_bfloat162 m = bb2;
#pragma unroll
            for (int h = 0; h < 8; h++) m = __hfma2(w8[h], hacc[h][pg], m);
            __nv_bfloat162 ev = h2exp2(m);
            e[pg][gg] = ev;
            float2 f = __bfloat1622float2(ev);
            zacc[pg & 1][gg] += f.x + f.y;
        }
    }

    // ---- E stores: transpose 8 pairs -> 2 uint4 per pair-group -------------
    uint4* Eg = reinterpret_cast<uint4*>(E);
#pragma unroll
    for (int pg = 0; pg < 4; pg++) {
        int nf = pg >> 1, hh = pg & 1;
        int row = wm + gq + hh * 8;
        int col = wn + nf * 8 + 2 * t;
        uint32_t lo[4], hi[4];
#pragma unroll
        for (int kk = 0; kk < 4; kk++) {
            uint32_t p0 = bf2_raw(e[pg][2 * kk]);
            uint32_t p1 = bf2_raw(e[pg][2 * kk + 1]);
            lo[kk] = __byte_perm(p0, p1, 0x5410);
            hi[kk] = __byte_perm(p0, p1, 0x7632);
        }
        size_t base = (size_t)(b * N_ + i0 + row) * N_ + j0 + col;
        Eg[base]     = make_uint4(lo[0], lo[1], lo[2], lo[3]);
        Eg[base + 1] = make_uint4(hi[0], hi[1], hi[2], hi[3]);
    }

    // ---- Z partial reduction over t lanes and store -------------------------
#pragma unroll
    for (int hh = 0; hh < 2; hh++)
#pragma unroll
        for (int gg = 0; gg < 8; gg++) {
            zacc[hh][gg] += __shfl_xor_sync(0xffffffffu, zacc[hh][gg], 1);
            zacc[hh][gg] += __shfl_xor_sync(0xffffffffu, zacc[hh][gg], 2);
        }
    if (t == 0) {
#pragma unroll
        for (int hh = 0; hh < 2; hh++) {
            int row = wm + gq + hh * 8;
            float* zp = Zp + (size_t)(b * N_ + i0 + row) * 512;
#pragma unroll
            for (int gg = 0; gg < 8; gg++) zp[gg * 64 + jb * 2 + wc] = zacc[hh][gg];
        }
    }
}

// ------------------- K2: normalize + packed postmix + AV --------------------
// grid (32 i-blocks, 8 b); 256 threads; dynamic smem 111904 B.
__global__ void __launch_bounds__(256, 2)
attn_pv_kernel(const bf16* __restrict__ E, const float* __restrict__ Zp,
               const bf16* __restrict__ vT, const float* __restrict__ ww,
               const float* __restrict__ bw, bf16* __restrict__ o)
{
    extern __shared__ char sm2[];
    bf16*  Vs   = reinterpret_cast<bf16*>(sm2);             // [8][64][72]
    bf16*  Pb   = reinterpret_cast<bf16*>(sm2 + 73728);     // [8][32][72]
    float* invZ = reinterpret_cast<float*>(sm2 + 110592);   // [32][8]
    __nv_bfloat162* wws2 = reinterpret_cast<__nv_bfloat162*>(sm2 + 111616);  // 64
    __nv_bfloat162* bws2 = reinterpret_cast<__nv_bfloat162*>(sm2 + 111872);  // 8

    const int tid = threadIdx.x;
    const int i0  = blockIdx.x * 32;
    const int b   = blockIdx.y;
    const int w = tid >> 5, l = tid & 31, gq = l >> 2, t = l & 3;
    const int wm = (w & 1) * 16;          // M 32
    const int wn = (w >> 1) * 16;         // N 64 padded (warps with wn=48 idle in mma)

    if (tid < 64) wws2[tid] = __float2bfloat162_rn(ww[tid]);
    if (tid < 8)  bws2[tid] = __float2bfloat162_rn(bw[tid]);
    {
        int i = tid >> 3, gg = tid & 7;
        const float* zp = Zp + (size_t)(b * N_ + i0 + i) * 512 + gg * 64;
        float s = 0.0f;
        for (int qq = 0; qq < 64; qq++) s += zp[qq];
        invZ[i * 8 + gg] = 1.0f / s;
    }
    __syncthreads();

    float acc[8][2][4];
    for (int gg = 0; gg < 8; gg++)
        for (int nf = 0; nf < 2; nf++)
            for (int e = 0; e < 4; e++) acc[gg][nf][e] = 0.0f;

    const int ei  = tid >> 3;     // row 0..31
    const int ej0 = tid & 7;
    const uint4* Eg = reinterpret_cast<const uint4*>(E);

    __nv_bfloat162 izr2[8];
    for (int hh = 0; hh < 8; hh++)
        izr2[hh] = __float2bfloat162_rn(invZ[ei * 8 + hh]);

    for (int jblk = 0; jblk < 16; jblk++) {
        const int j0 = jblk * 64;
        // E loads: 4 adjacent j-pairs per thread, j = 2*ej0 + 16*p (+1)
        uint4 evA[4], evB[4];
        size_t ebase = (size_t)(b * N_ + i0 + ei) * N_ + j0;
#pragma unroll
        for (int p = 0; p < 4; p++) {
            evA[p] = Eg[ebase + 2 * ej0 + 16 * p];
            evB[p] = Eg[ebase + 2 * ej0 + 16 * p + 1];
        }
        __syncthreads();    // previous mma done; smem reusable
        // V tiles: 8 g x 64 d-rows x 64 j
        for (int idx = tid; idx < 4096; idx += 256) {
            int gg = idx >> 9;
            int r  = (idx >> 3) & 63;
            int c  = (idx & 7) * 8;
            *reinterpret_cast<uint4*>(Vs + (gg * 64 + r) * 72 + c) =
                *reinterpret_cast<const uint4*>(vT + ((size_t)(b * H_ + gg) * 64 + r) * N_ + j0 + c);
        }
        // packed normalize + postmix, 2 pairs per half
#pragma unroll
        for (int half = 0; half < 2; half++) {
            __nv_bfloat162 ph2[2][8];
#pragma unroll
            for (int pp = 0; pp < 2; pp++) {
                int pi = half * 2 + pp;
                const uint32_t* Aw = reinterpret_cast<const uint32_t*>(&evA[pi]);
                const uint32_t* Bw = reinterpret_cast<const uint32_t*>(&evB[pi]);
#pragma unroll
                for (int kk = 0; kk < 4; kk++) {
                    uint32_t slo = __byte_perm(Aw[kk], Bw[kk], 0x5410);
                    uint32_t shi = __byte_perm(Aw[kk], Bw[kk], 0x7632);
                    ph2[pp][2 * kk]     = __hmul2(raw_bf2(slo), izr2[2 * kk]);
                    ph2[pp][2 * kk + 1] = __hmul2(raw_bf2(shi), izr2[2 * kk + 1]);
                }
            }
#pragma unroll
            for (int gg = 0; gg < 8; gg++) {
                __nv_bfloat162 pv0 = bws2[gg];
                __nv_bfloat162 pv1 = bws2[gg];
#pragma unroll
                for (int hh = 0; hh < 8; hh++) {
                    __nv_bfloat162 wv = wws2[gg * 8 + hh];
                    pv0 = __hfma2(wv, ph2[0][hh], pv0);
                    pv1 = __hfma2(wv, ph2[1][hh], pv1);
                }
                int j1 = 2 * ej0 + 16 * (half * 2 + 0);
                int j2 = 2 * ej0 + 16 * (half * 2 + 1);
                *reinterpret_cast<__nv_bfloat162*>(&Pb[(gg * 32 + ei) * 72 + j1]) = pv0;
                *reinterpret_cast<__nv_bfloat162*>(&Pb[(gg * 32 + ei) * 72 + j2]) = pv1;
            }
        }
        __syncthreads();
        // AV mma per output head
        if (wn < 48) {
            for (int gg = 0; gg < 8; gg++) {
                const bf16* Pg = Pb + gg * 32 * 72;
                const bf16* Vg = Vs + gg * 64 * 72;
                for (int k0 = 0; k0 < 64; k0 += 16) {
                    uint32_t a[4];
                    a[0] = *reinterpret_cast<const uint32_t*>(Pg + (wm + gq) * 72 + k0 + 2 * t);
                    a[1] = *reinterpret_cast<const uint32_t*>(Pg + (wm + gq + 8) * 72 + k0 + 2 * t);
                    a[2] = *reinterpret_cast<const uint32_t*>(Pg + (wm + gq) * 72 + k0 + 2 * t + 8);
                    a[3] = *reinterpret_cast<const uint32_t*>(Pg + (wm + gq + 8) * 72 + k0 + 2 * t + 8);
                    for (int nf = 0; nf < 2; nf++) {
                        uint32_t bb[2];
                        bb[0] = *reinterpret_cast<const uint32_t*>(Vg + (wn + nf * 8 + gq) * 72 + k0 + 2 * t);
                        bb[1] = *reinterpret_cast<const uint32_t*>(Vg + (wn + nf * 8 + gq) * 72 + k0 + 2 * t + 8);
                        mma16816(acc[gg][nf], a, bb);
                    }
                }
            }
        }
    }

    if (wn < 48) {
        for (int gg = 0; gg < 8; gg++) {
            for (int nf = 0; nf < 2; nf++) {
                for (int hh = 0; hh < 2; hh++) {
                    int row = wm + gq + hh * 8;
                    int col = wn + nf * 8 + 2 * t;
                    if (col < HD_) {
                        __nv_bfloat162 p = __floats2bfloat162_rn(acc[gg][nf][hh * 2 + 0],
                                                                 acc[gg][nf][hh * 2 + 1]);
                        *reinterpret_cast<__nv_bfloat162*>(
                            &o[(size_t)(b * N_ + i0 + row) * D_ + gg * HD_ + col]) = p;
                    }
                }
            }
        }
    }
}

// ------------------- host launcher ------------------------------------------
extern "C" void kernel_launch(void* const* d_in, const int* in_sizes, int n_in,
                              void* d_out, int out_size)
{
    (void)in_sizes; (void)n_in; (void)out_size;
    const float* x      = (const float*)d_in[0];
    const float* ln1_g  = (const float*)d_in[1];
    const float* ln1_b  = (const float*)d_in[2];
    const float* w_qkv  = (const float*)d_in[3];
    const float* w_proj = (const float*)d_in[4];
    const float* b_proj = (const float*)d_in[5];
    const float* w_l    = (const float*)d_in[6];
    const float* b_l    = (const float*)d_in[7];
    const float* w_w    = (const float*)d_in[8];
    const float* b_w    = (const float*)d_in[9];
    const float* ln2_g  = (const float*)d_in[10];
    const float* ln2_b  = (const float*)d_in[11];
    const float* w_fc1  = (const float*)d_in[12];
    const float* b_fc1  = (const float*)d_in[13];
    const float* w_fc2  = (const float*)d_in[14];
    const float* b_fc2  = (const float*)d_in[15];
    const float* gamma1 = (const float*)d_in[16];
    const float* gamma2 = (const float*)d_in[17];
    float* out = (float*)d_out;

    bf16 *hb, *act, *qb, *kb, *vT, *E, *o, *wqkvb, *wprojb, *wfc1b, *wfc2b;
    float *x1, *Zp;
    cudaGetSymbolAddress((void**)&hb,     g_hb);
    cudaGetSymbolAddress((void**)&act,    g_act);
    cudaGetSymbolAddress((void**)&qb,     g_q);
    cudaGetSymbolAddress((void**)&kb,     g_k);
    cudaGetSymbolAddress((void**)&vT,     g_vT);
    cudaGetSymbolAddress((void**)&E,      g_E);
    cudaGetSymbolAddress((void**)&Zp,     g_Zp);
    cudaGetSymbolAddress((void**)&o,      g_o);
    cudaGetSymbolAddress((void**)&x1,     g_x1);
    cudaGetSymbolAddress((void**)&wqkvb,  g_wqkv);
    cudaGetSymbolAddress((void**)&wprojb, g_wproj);
    cudaGetSymbolAddress((void**)&wfc1b,  g_wfc1);
    cudaGetSymbolAddress((void**)&wfc2b,  g_wfc2);

    cudaFuncSetAttribute(attn_pv_kernel, cudaFuncAttributeMaxDynamicSharedMemorySize, 111904);

    cvt_all_kernel<<<1728, 256>>>(w_qkv, wqkvb, w_proj, wprojb,
                                  w_fc1, wfc1b, w_fc2, wfc2b);

    ln_kernel<<<ROWS, 128>>>(x, ln1_g, ln1_b, hb);

    gemm_kernel<128, 128, 0><<<dim3(9, 64, 1), 256>>>(
        hb, wqkvb, ROWS, 1152, 384, 384, 384,
        nullptr, nullptr, nullptr, nullptr, nullptr, qb, kb, vT);

    score_mix_kernel<<<dim3(32, 16, 8), 256>>>(qb, kb, w_l, b_l, E, Zp);

    attn_pv_kernel<<<dim3(32, 8), 256, 111904>>>(E, Zp, vT, w_w, b_w, o);

    gemm_kernel<64, 128, 4><<<dim3(3, 128, 1), 256>>>(
        o, wprojb, ROWS, D_, D_, D_, D_,
        b_proj, x, gamma1, x1, nullptr, nullptr, nullptr, nullptr);

    ln_kernel<<<ROWS, 128>>>(x1, ln2_g, ln2_b, hb);

    gemm_kernel<128, 128, 3><<<dim3(12, 64, 1), 256>>>(
        hb, wfc1b, ROWS, HID_, D_, D_, D_,
        b_fc1, nullptr, nullptr, nullptr, act, nullptr, nullptr, nullptr);

    gemm_kernel<64, 128, 4><<<dim3(3, 128, 1), 256>>>(
        act, wfc2b, ROWS, D_, HID_, HID_, HID_,
        b_fc2, x1, gamma2, out, nullptr, nullptr, nullptr, nullptr);
}

// round 13
// speedup vs baseline: 1.1822x; 1.1822x over previous
#include <cuda_runtime.h>
#include <cuda_bf16.h>
#include <cstdint>
#include <math.h>

typedef __nv_bfloat16 bf16;

#define B_   8
#define N_   1024
#define D_   384
#define H_   8
#define HD_  48
#define HID_ 1536
#define ROWS 8192
#define QSCALE 0.14433756729740643f
#define LOG2E 1.4426950408889634f

// ------------------- static scratch (no allocation allowed) -----------------
__device__ bf16  g_hb  [ROWS * D_];
__device__ bf16  g_act [ROWS * HID_];
__device__ bf16  g_q   [B_ * H_ * N_ * HD_];
__device__ bf16  g_k   [B_ * H_ * N_ * HD_];
__device__ bf16  g_vT  [B_ * H_ * 64 * N_];   // zero-init; pad rows 48..63 never written
__device__ bf16  g_E   [(size_t)B_ * N_ * N_ * H_];   // exp(premixed logits), (b,i,j,h)
__device__ float g_Zp  [B_ * N_ * H_ * 16];           // Z partials per j-block
__device__ bf16  g_o   [ROWS * D_];
__device__ float g_x1  [ROWS * D_];
__device__ bf16  g_wqkv [3 * D_ * D_];
__device__ bf16  g_wproj[D_ * D_];
__device__ bf16  g_wfc1 [HID_ * D_];
__device__ bf16  g_wfc2 [D_ * HID_];

// ------------------- fused fp32 -> bf16 convert for all 4 weights -----------
__global__ void cvt_all_kernel(const float* w0, bf16* o0, const float* w1, bf16* o1,
                               const float* w2, bf16* o2, const float* w3, bf16* o3)
{
    int i = blockIdx.x * 256 + threadIdx.x;            // float4 index
    const float* src;
    bf16* dst;
    int base;
    if (i < 110592)       { src = w0; dst = o0; base = i; }
    else if (i < 147456)  { src = w1; dst = o1; base = i - 110592; }
    else if (i < 294912)  { src = w2; dst = o2; base = i - 147456; }
    else if (i < 442368)  { src = w3; dst = o3; base = i - 294912; }
    else return;
    float4 v = reinterpret_cast<const float4*>(src)[base];
    reinterpret_cast<__nv_bfloat162*>(dst)[2 * base]     = __floats2bfloat162_rn(v.x, v.y);
    reinterpret_cast<__nv_bfloat162*>(dst)[2 * base + 1] = __floats2bfloat162_rn(v.z, v.w);
}

// ------------------- LayerNorm fp32 -> bf16 ---------------------------------
__global__ void ln_kernel(const float* __restrict__ x, const float* __restrict__ gw,
                          const float* __restrict__ bw, bf16* __restrict__ out)
{
    int row = blockIdx.x;
    int t   = threadIdx.x;
    const float* xr = x + (size_t)row * D_;
    float v0 = xr[t], v1 = xr[t + 128], v2 = xr[t + 256];
    float s  = v0 + v1 + v2;
    float ss = v0 * v0 + v1 * v1 + v2 * v2;
    for (int o = 16; o > 0; o >>= 1) {
        s  += __shfl_xor_sync(0xffffffffu, s,  o);
        ss += __shfl_xor_sync(0xffffffffu, ss, o);
    }
    __shared__ float rs[4];
    __shared__ float rq[4];
    if ((t & 31) == 0) { rs[t >> 5] = s; rq[t >> 5] = ss; }
    __syncthreads();
    s  = rs[0] + rs[1] + rs[2] + rs[3];
    ss = rq[0] + rq[1] + rq[2] + rq[3];
    float mean = s * (1.0f / 384.0f);
    float var  = ss * (1.0f / 384.0f) - mean * mean;
    float rstd = rsqrtf(var + 1e-5f);
    bf16* orow = out + (size_t)row * D_;
    orow[t]       = __float2bfloat16((v0 - mean) * rstd * gw[t]       + bw[t]);
    orow[t + 128] = __float2bfloat16((v1 - mean) * rstd * gw[t + 128] + bw[t + 128]);
    orow[t + 256] = __float2bfloat16((v2 - mean) * rstd * gw[t + 256] + bw[t + 256]);
}

// ------------------- PTX helpers --------------------------------------------
__device__ __forceinline__ void mma16816(float* c, const uint32_t* a, const uint32_t* b)
{
    asm volatile(
        "mma.sync.aligned.m16n8k16.row.col.f32.bf16.bf16.f32 "
        "{%0,%1,%2,%3}, {%4,%5,%6,%7}, {%8,%9}, {%0,%1,%2,%3};\n"
        : "+f"(c[0]), "+f"(c[1]), "+f"(c[2]), "+f"(c[3])
        : "r"(a[0]), "r"(a[1]), "r"(a[2]), "r"(a[3]), "r"(b[0]), "r"(b[1]));
}

__device__ __forceinline__ void cp_async16(uint32_t dst, const void* src)
{
    asm volatile("cp.async.cg.shared.global [%0], [%1], 16;\n" :: "r"(dst), "l"(src));
}
__device__ __forceinline__ void cp_commit()
{
    asm volatile("cp.async.commit_group;\n");
}
__device__ __forceinline__ void cp_wait0()
{
    asm volatile("cp.async.wait_group 0;\n" ::: "memory");
}
__device__ __forceinline__ void cp_wait1()
{
    asm volatile("cp.async.wait_group 1;\n" ::: "memory");
}

__device__ __forceinline__ float ex2f(float x)
{
    float y;
    asm("ex2.approx.f32 %0, %1;" : "=f"(y) : "f"(x));
    return y;
}
__device__ __forceinline__ float rcpf(float x)
{
    float y;
    asm("rcp.approx.f32 %0, %1;" : "=f"(y) : "f"(x));
    return y;
}
__device__ __forceinline__ uint32_t ex2_bf2(uint32_t x)
{
    uint32_t y;
    asm("ex2.approx.ftz.bf16x2 %0, %1;" : "=r"(y) : "r"(x));
    return y;
}

__device__ __forceinline__ uint32_t bf2_raw(__nv_bfloat162 v)
{
    return *reinterpret_cast<uint32_t*>(&v);
}
__device__ __forceinline__ __nv_bfloat162 raw_bf2(uint32_t v)
{
    return *reinterpret_cast<__nv_bfloat162*>(&v);
}

// ------------------- tensor-core GEMM  C = A @ B^T --------------------------
// 3-stage cp.async pipeline, 256 threads. MODE 0: qkv scatter; MODE 3: GELU;
// MODE 4: bias + residual + layerscale.
template<int BM, int BN, int MODE>
__global__ void __launch_bounds__(256)
gemm_kernel(const bf16* __restrict__ A, const bf16* __restrict__ Bw,
            int M, int N, int K, int lda, int ldb,
            const float* __restrict__ bias, const float* __restrict__ resid,
            const float* __restrict__ gamma, float* __restrict__ fout,
            bf16* __restrict__ bout, bf16* __restrict__ qo,
            bf16* __restrict__ ko, bf16* __restrict__ vo)
{
    constexpr int WM_CNT = BM / 32;
    constexpr int WN_TILE = BN * WM_CNT / 8;
    constexpr int NT = WN_TILE / 8;
    constexpr int A_STAGE = BM * 24;
    constexpr int B_STAGE = BN * 24;

    __shared__ bf16 As[3][BM][24];
    __shared__ bf16 Bs[3][BN][24];

    const int tid = threadIdx.x;
    const int w = tid >> 5;
    const int l = tid & 31;
    const int g = l >> 2;
    const int t = l & 3;
    const int wm = (w % WM_CNT) * 32;
    const int wn = (w / WM_CNT) * WN_TILE;
    const int m0 = blockIdx.y * BM;
    const int n0 = blockIdx.x * BN;

    const bf16* Ap = A;
    const bf16* Bp = Bw;

    const int arow = tid >> 1;
    const int acg  = (tid & 1) * 8;
    const int brow = tid >> 1;
    const int bcg  = (tid & 1) * 8;
    const bool doA = (tid < BM * 2);
    const bool doB = (tid < BN * 2);

    const bf16* aSrc = Ap + (size_t)(m0 + (doA ? arow : 0)) * lda + acg;
    const bf16* bSrc = Bp + (size_t)(n0 + (doB ? brow : 0)) * ldb + bcg;
    const uint32_t aDst0 = (uint32_t)__cvta_generic_to_shared(&As[0][doA ? arow : 0][acg]);
    const uint32_t bDst0 = (uint32_t)__cvta_generic_to_shared(&Bs[0][doB ? brow : 0][bcg]);

    float acc[2][NT][4];
    for (int mi = 0; mi < 2; mi++)
        for (int ni = 0; ni < NT; ni++)
            for (int e = 0; e < 4; e++)
                acc[mi][ni][e] = 0.0f;

    const int niter = K >> 4;

    if (doA) cp_async16(aDst0, aSrc);
    if (doB) cp_async16(bDst0, bSrc);
    cp_commit();
    if (niter > 1) {
        if (doA) cp_async16(aDst0 + A_STAGE * 2, aSrc + 16);
        if (doB) cp_async16(bDst0 + B_STAGE * 2, bSrc + 16);
    }
    cp_commit();

    int buf = 0;
    for (int it = 0; it < niter; it++) {
        cp_wait1();
        __syncthreads();
        {
            int pf = buf + 2; if (pf >= 3) pf -= 3;
            if (it + 2 < niter) {
                int kn = (it + 2) << 4;
                if (doA) cp_async16(aDst0 + (uint32_t)pf * (A_STAGE * 2), aSrc + kn);
                if (doB) cp_async16(bDst0 + (uint32_t)pf * (B_STAGE * 2), bSrc + kn);
            }
            cp_commit();
        }

        const bf16 (*Ab)[24] = As[buf];
        const bf16 (*Bb)[24] = Bs[buf];

        uint32_t af[2][4];
        for (int mi = 0; mi < 2; mi++) {
            int r = wm + mi * 16 + g;
            af[mi][0] = *reinterpret_cast<const uint32_t*>(&Ab[r][2 * t]);
            af[mi][1] = *reinterpret_cast<const uint32_t*>(&Ab[r + 8][2 * t]);
            af[mi][2] = *reinterpret_cast<const uint32_t*>(&Ab[r][2 * t + 8]);
            af[mi][3] = *reinterpret_cast<const uint32_t*>(&Ab[r + 8][2 * t + 8]);
        }
        uint32_t bfm[NT][2];
        for (int ni = 0; ni < NT; ni++) {
            int c = wn + ni * 8 + g;
            bfm[ni][0] = *reinterpret_cast<const uint32_t*>(&Bb[c][2 * t]);
            bfm[ni][1] = *reinterpret_cast<const uint32_t*>(&Bb[c][2 * t + 8]);
        }
        for (int mi = 0; mi < 2; mi++)
            for (int ni = 0; ni < NT; ni++)
                mma16816(acc[mi][ni], af[mi], bfm[ni]);

        buf++; if (buf == 3) buf = 0;
    }

    for (int mi = 0; mi < 2; mi++) {
        for (int ni = 0; ni < NT; ni++) {
            for (int hh = 0; hh < 2; hh++) {
                int row = m0 + wm + mi * 16 + g + hh * 8;
                int col = n0 + wn + ni * 8 + 2 * t;
                float v0 = acc[mi][ni][hh * 2 + 0];
                float v1 = acc[mi][ni][hh * 2 + 1];
                if (MODE == 0) {
                    int t3 = col / D_;
                    int r  = col - t3 * D_;
                    int hd = r / HD_;
                    int dd = r - hd * HD_;
                    int bb = row >> 10;
                    int ii = row & 1023;
                    size_t qk = ((size_t)(bb * H_ + hd) * N_ + ii) * HD_ + dd;
                    if (t3 == 0) {
                        __nv_bfloat162 p = __floats2bfloat162_rn(v0 * QSCALE, v1 * QSCALE);
                        *reinterpret_cast<__nv_bfloat162*>(&qo[qk]) = p;
                    } else if (t3 == 1) {
                        __nv_bfloat162 p = __floats2bfloat162_rn(v0, v1);
                        *reinterpret_cast<__nv_bfloat162*>(&ko[qk]) = p;
                    } else {
                        size_t vb = ((size_t)(bb * H_ + hd) * 64 + dd) * N_ + ii;
                        vo[vb]      = __float2bfloat16(v0);
                        vo[vb + N_] = __float2bfloat16(v1);
                    }
                } else if (MODE == 3) {
                    // GELU via sigmoid approximation: x * sigmoid(1.702 x)
                    float a0 = v0 + bias[col];
                    float a1 = v1 + bias[col + 1];
                    float s0 = rcpf(1.0f + ex2f(-1.702f * LOG2E * a0));
                    float s1 = rcpf(1.0f + ex2f(-1.702f * LOG2E * a1));
                    a0 *= s0;
                    a1 *= s1;
                    __nv_bfloat162 p = __floats2bfloat162_rn(a0, a1);
                    *reinterpret_cast<__nv_bfloat162*>(&bout[(size_t)row * N + col]) = p;
                } else {
                    float2 rr = *reinterpret_cast<const float2*>(&resid[(size_t)row * N + col]);
                    float2 o2;
                    o2.x = rr.x + gamma[col]     * (v0 + bias[col]);
                    o2.y = rr.y + gamma[col + 1] * (v1 + bias[col + 1]);
                    *reinterpret_cast<float2*>(&fout[(size_t)row * N + col]) = o2;
                }
            }
        }
    }
}

// ------------------- K1: QK^T (8 heads) + packed premix + exp + Z -----------
// grid (16 jb, 16 ib, 8 b); 256 threads; tile 64x64; dynamic smem 97056 B.
// Es layout: (row, h, j) at row*532 + h*66 + j  (bf16; packed bf16x2 pairs on j)
__global__ void __launch_bounds__(256)
score_mix_kernel(const bf16* __restrict__ q, const bf16* __restrict__ k,
                 const float* __restrict__ wl, const float* __restrict__ bl,
                 bf16* __restrict__ E, float* __restrict__ Zp)
{
    extern __shared__ char sm1[];
    bf16*  Qs  = reinterpret_cast<bf16*>(sm1);            // [2][64][56] 14336 B
    bf16*  Ks  = reinterpret_cast<bf16*>(sm1 + 14336);    // [2][64][56] 14336 B
    bf16*  Es  = reinterpret_cast<bf16*>(sm1 + 28672);    // [64][532]   68096 B
    __nv_bfloat162* wls2 = reinterpret_cast<__nv_bfloat162*>(sm1 + 96768);  // 64
    __nv_bfloat162* bls2 = reinterpret_cast<__nv_bfloat162*>(sm1 + 97024);  // 8

    const int tid = threadIdx.x;
    const int jb  = blockIdx.x;
    const int j0  = jb * 64;
    const int i0  = blockIdx.y * 64;
    const int b   = blockIdx.z;

    if (tid < 64) wls2[tid] = __float2bfloat162_rn(wl[tid] * LOG2E);
    if (tid < 8)  bls2[tid] = __float2bfloat162_rn(bl[tid] * LOG2E);

    const int w = tid >> 5, l = tid & 31, gq = l >> 2, t = l & 3;
    const int wm = (w & 3) * 16;          // M 64: 4 warp rows
    const int wn = (w >> 2) * 32;         // N 64: 2 warp cols of 32

    auto loadQK = [&](int h, int buf) {
        const bf16* qsrc = q + ((size_t)(b * H_ + h) * N_ + i0) * HD_;
        const bf16* ksrc = k + ((size_t)(b * H_ + h) * N_ + j0) * HD_;
        for (int idx = tid; idx < 384; idx += 256) {
            int r = idx / 6;
            int c = (idx - r * 6) * 8;
            cp_async16((uint32_t)__cvta_generic_to_shared(Qs + buf * 3584 + r * 56 + c),
                       qsrc + (size_t)r * HD_ + c);
            cp_async16((uint32_t)__cvta_generic_to_shared(Ks + buf * 3584 + r * 56 + c),
                       ksrc + (size_t)r * HD_ + c);
        }
    };

    loadQK(0, 0);
    cp_commit();

    for (int h = 0; h < 8; h++) {
        cp_wait0();
        __syncthreads();
        if (h + 1 < 8) loadQK(h + 1, (h + 1) & 1);
        cp_commit();

        const bf16* Qb = Qs + (h & 1) * 3584;
        const bf16* Kb = Ks + (h & 1) * 3584;

        float acc[4][4];
        for (int nf = 0; nf < 4; nf++)
            for (int e = 0; e < 4; e++) acc[nf][e] = 0.0f;

        for (int k0 = 0; k0 < 48; k0 += 16) {
            uint32_t a[4];
            a[0] = *reinterpret_cast<const uint32_t*>(Qb + (wm + gq) * 56 + k0 + 2 * t);
            a[1] = *reinterpret_cast<const uint32_t*>(Qb + (wm + gq + 8) * 56 + k0 + 2 * t);
            a[2] = *reinterpret_cast<const uint32_t*>(Qb + (wm + gq) * 56 + k0 + 2 * t + 8);
            a[3] = *reinterpret_cast<const uint32_t*>(Qb + (wm + gq + 8) * 56 + k0 + 2 * t + 8);
            for (int nf = 0; nf < 4; nf++) {
                uint32_t bb[2];
                bb[0] = *reinterpret_cast<const uint32_t*>(Kb + (wn + nf * 8 + gq) * 56 + k0 + 2 * t);
                bb[1] = *reinterpret_cast<const uint32_t*>(Kb + (wn + nf * 8 + gq) * 56 + k0 + 2 * t + 8);
                mma16816(acc[nf], a, bb);
            }
        }
        // stage this head's scores as packed (j, j+1) bf16x2 into Es[row][h][col]
        for (int nf = 0; nf < 4; nf++) {
            for (int hh = 0; hh < 2; hh++) {
                int row = wm + gq + hh * 8;
                int col = wn + nf * 8 + 2 * t;
                __nv_bfloat162 pr = __floats2bfloat162_rn(acc[nf][hh * 2 + 0],
                                                          acc[nf][hh * 2 + 1]);
                *reinterpret_cast<__nv_bfloat162*>(&Es[row * 532 + h * 66 + col]) = pr;
            }
        }
    }
    __syncthreads();

    // packed premix + exp2 + E store + Z. thread: row mi, j-pairs 2*mj0 + 8p
    const int mi  = tid >> 2;
    const int mj0 = tid & 3;
    __nv_bfloat162 zacc2[8];
    for (int gg = 0; gg < 8; gg++) zacc2[gg] = __float2bfloat162_rn(0.0f);

    uint4* Eg = reinterpret_cast<uint4*>(E);
    for (int p = 0; p < 8; p++) {
        int j = 2 * mj0 + 8 * p;
        uint32_t s2[8];
#pragma unroll
        for (int hh = 0; hh < 8; hh++)
            s2[hh] = *reinterpret_cast<const uint32_t*>(&Es[mi * 532 + hh * 66 + j]);
        uint32_t e2[8];
#pragma unroll
        for (int gg = 0; gg < 8; gg++) {
            __nv_bfloat162 m = bls2[gg];
#pragma unroll
            for (int hh = 0; hh < 8; hh++)
                m = __hfma2(wls2[gg * 8 + hh], raw_bf2(s2[hh]), m);
            uint32_t ev = ex2_bf2(bf2_raw(m));
            e2[gg] = ev;
            zacc2[gg] = __hadd2(zacc2[gg], raw_bf2(ev));
        }
        uint32_t lo[4], hi[4];
#pragma unroll
        for (int kk = 0; kk < 4; kk++) {
            lo[kk] = __byte_perm(e2[2 * kk], e2[2 * kk + 1], 0x5410);
            hi[kk] = __byte_perm(e2[2 * kk], e2[2 * kk + 1], 0x7632);
        }
        size_t base = (size_t)(b * N_ + i0 + mi) * N_ + j0 + j;
        Eg[base]     = make_uint4(lo[0], lo[1], lo[2], lo[3]);
        Eg[base + 1] = make_uint4(hi[0], hi[1], hi[2], hi[3]);
    }
    // Z: convert packed accumulators, reduce over the 4 lanes sharing a row
    float zf[8];
#pragma unroll
    for (int gg = 0; gg < 8; gg++) {
        float2 f = __bfloat1622float2(zacc2[gg]);
        zf[gg] = f.x + f.y;
        zf[gg] += __shfl_xor_sync(0xffffffffu, zf[gg], 1);
        zf[gg] += __shfl_xor_sync(0xffffffffu, zf[gg], 2);
    }
    if ((tid & 3) == 0) {
        float* zp = Zp + (size_t)(b * N_ + i0 + mi) * 128 + jb;
#pragma unroll
        for (int gg = 0; gg < 8; gg++) zp[gg * 16] = zf[gg];
    }
}

// ------------------- K2: normalize + packed postmix + AV --------------------
// grid (32 i-blocks, 8 b); 256 threads; dynamic smem 111904 B.
__global__ void __launch_bounds__(256, 2)
attn_pv_kernel(const bf16* __restrict__ E, const float* __restrict__ Zp,
               const bf16* __restrict__ vT, const float* __restrict__ ww,
               const float* __restrict__ bw, bf16* __restrict__ o)
{
    extern __shared__ char sm2[];
    bf16*  Vs   = reinterpret_cast<bf16*>(sm2);             // [8][64][72]
    bf16*  Pb   = reinterpret_cast<bf16*>(sm2 + 73728);     // [8][32][72]
    float* invZ = reinterpret_cast<float*>(sm2 + 110592);   // [32][8]
    __nv_bfloat162* wws2 = reinterpret_cast<__nv_bfloat162*>(sm2 + 111616);  // 64
    __nv_bfloat162* bws2 = reinterpret_cast<__nv_bfloat162*>(sm2 + 111872);  // 8

    const int tid = threadIdx.x;
    const int i0  = blockIdx.x * 32;
    const int b   = blockIdx.y;
    const int w = tid >> 5, l = tid & 31, gq = l >> 2, t = l & 3;
    const int wm = (w & 1) * 16;          // M 32
    const int wn = (w >> 1) * 16;         // N 64 padded (warps with wn=48 idle in mma)

    if (tid < 64) wws2[tid] = __float2bfloat162_rn(ww[tid]);
    if (tid < 8)  bws2[tid] = __float2bfloat162_rn(bw[tid]);
    {
        int i = tid >> 3, gg = tid & 7;
        const float* zp = Zp + (size_t)(b * N_ + i0 + i) * 128 + gg * 16;
        float s = 0.0f;
        for (int qq = 0; qq < 16; qq++) s += zp[qq];
        invZ[i * 8 + gg] = 1.0f / s;
    }
    __syncthreads();

    float acc[8][2][4];
    for (int gg = 0; gg < 8; gg++)
        for (int nf = 0; nf < 2; nf++)
            for (int e = 0; e < 4; e++) acc[gg][nf][e] = 0.0f;

    const int ei  = tid >> 3;     // row 0..31
    const int ej0 = tid & 7;
    const uint4* Eg = reinterpret_cast<const uint4*>(E);

    __nv_bfloat162 izr2[8];
    for (int hh = 0; hh < 8; hh++)
        izr2[hh] = __float2bfloat162_rn(invZ[ei * 8 + hh]);

    for (int jblk = 0; jblk < 16; jblk++) {
        const int j0 = jblk * 64;
        uint4 evA[4], evB[4];
        size_t ebase = (size_t)(b * N_ + i0 + ei) * N_ + j0;
#pragma unroll
        for (int p = 0; p < 4; p++) {
            evA[p] = Eg[ebase + 2 * ej0 + 16 * p];
            evB[p] = Eg[ebase + 2 * ej0 + 16 * p + 1];
        }
        __syncthreads();    // previous mma done; smem reusable
        for (int idx = tid; idx < 4096; idx += 256) {
            int gg = idx >> 9;
            int r  = (idx >> 3) & 63;
            int c  = (idx & 7) * 8;
            *reinterpret_cast<uint4*>(Vs + (gg * 64 + r) * 72 + c) =
                *reinterpret_cast<const uint4*>(vT + ((size_t)(b * H_ + gg) * 64 + r) * N_ + j0 + c);
        }
#pragma unroll
        for (int half = 0; half < 2; half++) {
            __nv_bfloat162 ph2[2][8];
#pragma unroll
            for (int pp = 0; pp < 2; pp++) {
                int pi = half * 2 + pp;
                const uint32_t* Aw = reinterpret_cast<const uint32_t*>(&evA[pi]);
                const uint32_t* Bw = reinterpret_cast<const uint32_t*>(&evB[pi]);
#pragma unroll
                for (int kk = 0; kk < 4; kk++) {
                    uint32_t slo = __byte_perm(Aw[kk], Bw[kk], 0x5410);
                    uint32_t shi = __byte_perm(Aw[kk], Bw[kk], 0x7632);
                    ph2[pp][2 * kk]     = __hmul2(raw_bf2(slo), izr2[2 * kk]);
                    ph2[pp][2 * kk + 1] = __hmul2(raw_bf2(shi), izr2[2 * kk + 1]);
                }
            }
#pragma unroll
            for (int gg = 0; gg < 8; gg++) {
                __nv_bfloat162 pv0 = bws2[gg];
                __nv_bfloat162 pv1 = bws2[gg];
#pragma unroll
                for (int hh = 0; hh < 8; hh++) {
                    __nv_bfloat162 wv = wws2[gg * 8 + hh];
                    pv0 = __hfma2(wv, ph2[0][hh], pv0);
                    pv1 = __hfma2(wv, ph2[1][hh], pv1);
                }
                int j1 = 2 * ej0 + 16 * (half * 2 + 0);
                int j2 = 2 * ej0 + 16 * (half * 2 + 1);
                *reinterpret_cast<__nv_bfloat162*>(&Pb[(gg * 32 + ei) * 72 + j1]) = pv0;
                *reinterpret_cast<__nv_bfloat162*>(&Pb[(gg * 32 + ei) * 72 + j2]) = pv1;
            }
        }
        __syncthreads();
        if (wn < 48) {
            for (int gg = 0; gg < 8; gg++) {
                const bf16* Pg = Pb + gg * 32 * 72;
                const bf16* Vg = Vs + gg * 64 * 72;
                for (int k0 = 0; k0 < 64; k0 += 16) {
                    uint32_t a[4];
                    a[0] = *reinterpret_cast<const uint32_t*>(Pg + (wm + gq) * 72 + k0 + 2 * t);
                    a[1] = *reinterpret_cast<const uint32_t*>(Pg + (wm + gq + 8) * 72 + k0 + 2 * t);
                    a[2] = *reinterpret_cast<const uint32_t*>(Pg + (wm + gq) * 72 + k0 + 2 * t + 8);
                    a[3] = *reinterpret_cast<const uint32_t*>(Pg + (wm + gq + 8) * 72 + k0 + 2 * t + 8);
                    for (int nf = 0; nf < 2; nf++) {
                        uint32_t bb[2];
                        bb[0] = *reinterpret_cast<const uint32_t*>(Vg + (wn + nf * 8 + gq) * 72 + k0 + 2 * t);
                        bb[1] = *reinterpret_cast<const uint32_t*>(Vg + (wn + nf * 8 + gq) * 72 + k0 + 2 * t + 8);
                        mma16816(acc[gg][nf], a, bb);
                    }
                }
            }
        }
    }

    if (wn < 48) {
        for (int gg = 0; gg < 8; gg++) {
            for (int nf = 0; nf < 2; nf++) {
                for (int hh = 0; hh < 2; hh++) {
                    int row = wm + gq + hh * 8;
                    int col = wn + nf * 8 + 2 * t;
                    if (col < HD_) {
                        __nv_bfloat162 p = __floats2bfloat162_rn(acc[gg][nf][hh * 2 + 0],
                                                                 acc[gg][nf][hh * 2 + 1]);
                        *reinterpret_cast<__nv_bfloat162*>(
                            &o[(size_t)(b * N_ + i0 + row) * D_ + gg * HD_ + col]) = p;
                    }
                }
            }
        }
    }
}

// ------------------- host launcher ------------------------------------------
extern "C" void kernel_launch(void* const* d_in, const int* in_sizes, int n_in,
                              void* d_out, int out_size)
{
    (void)in_sizes; (void)n_in; (void)out_size;
    const float* x      = (const float*)d_in[0];
    const float* ln1_g  = (const float*)d_in[1];
    const float* ln1_b  = (const float*)d_in[2];
    const float* w_qkv  = (const float*)d_in[3];
    const float* w_proj = (const float*)d_in[4];
    const float* b_proj = (const float*)d_in[5];
    const float* w_l    = (const float*)d_in[6];
    const float* b_l    = (const float*)d_in[7];
    const float* w_w    = (const float*)d_in[8];
    const float* b_w    = (const float*)d_in[9];
    const float* ln2_g  = (const float*)d_in[10];
    const float* ln2_b  = (const float*)d_in[11];
    const float* w_fc1  = (const float*)d_in[12];
    const float* b_fc1  = (const float*)d_in[13];
    const float* w_fc2  = (const float*)d_in[14];
    const float* b_fc2  = (const float*)d_in[15];
    const float* gamma1 = (const float*)d_in[16];
    const float* gamma2 = (const float*)d_in[17];
    float* out = (float*)d_out;

    bf16 *hb, *act, *qb, *kb, *vT, *E, *o, *wqkvb, *wprojb, *wfc1b, *wfc2b;
    float *x1, *Zp;
    cudaGetSymbolAddress((void**)&hb,     g_hb);
    cudaGetSymbolAddress((void**)&act,    g_act);
    cudaGetSymbolAddress((void**)&qb,     g_q);
    cudaGetSymbolAddress((void**)&kb,     g_k);
    cudaGetSymbolAddress((void**)&vT,     g_vT);
    cudaGetSymbolAddress((void**)&E,      g_E);
    cudaGetSymbolAddress((void**)&Zp,     g_Zp);
    cudaGetSymbolAddress((void**)&o,      g_o);
    cudaGetSymbolAddress((void**)&x1,     g_x1);
    cudaGetSymbolAddress((void**)&wqkvb,  g_wqkv);
    cudaGetSymbolAddress((void**)&wprojb, g_wproj);
    cudaGetSymbolAddress((void**)&wfc1b,  g_wfc1);
    cudaGetSymbolAddress((void**)&wfc2b,  g_wfc2);

    cudaFuncSetAttribute(score_mix_kernel, cudaFuncAttributeMaxDynamicSharedMemorySize, 97056);
    cudaFuncSetAttribute(attn_pv_kernel,   cudaFuncAttributeMaxDynamicSharedMemorySize, 111904);

    cvt_all_kernel<<<1728, 256>>>(w_qkv, wqkvb, w_proj, wprojb,
                                  w_fc1, wfc1b, w_fc2, wfc2b);

    ln_kernel<<<ROWS, 128>>>(x, ln1_g, ln1_b, hb);

    gemm_kernel<128, 128, 0><<<dim3(9, 64, 1), 256>>>(
        hb, wqkvb, ROWS, 1152, 384, 384, 384,
        nullptr, nullptr, nullptr, nullptr, nullptr, qb, kb, vT);

    score_mix_kernel<<<dim3(16, 16, 8), 256, 97056>>>(qb, kb, w_l, b_l, E, Zp);

    attn_pv_kernel<<<dim3(32, 8), 256, 111904>>>(E, Zp, vT, w_w, b_w, o);

    gemm_kernel<64, 128, 4><<<dim3(3, 128, 1), 256>>>(
        o, wprojb, ROWS, D_, D_, D_, D_,
        b_proj, x, gamma1, x1, nullptr, nullptr, nullptr, nullptr);

    ln_kernel<<<ROWS, 128>>>(x1, ln2_g, ln2_b, hb);

    gemm_kernel<128, 128, 3><<<dim3(12, 64, 1), 256>>>(
        hb, wfc1b, ROWS, HID_, D_, D_, D_,
        b_fc1, nullptr, nullptr, nullptr, act, nullptr, nullptr, nullptr);

    gemm_kernel<64, 128, 4><<<dim3(3, 128, 1), 256>>>(
        act, wfc2b, ROWS, D_, HID_, HID_, HID_,
        b_fc2, x1, gamma2, out, nullptr, nullptr, nullptr, nullptr);
}

// round 14
// speedup vs baseline: 1.1923x; 1.0085x over previous
#include <cuda_runtime.h>
#include <cuda_bf16.h>
#include <cstdint>
#include <math.h>

typedef __nv_bfloat16 bf16;

#define B_   8
#define N_   1024
#define D_   384
#define H_   8
#define HD_  48
#define HID_ 1536
#define ROWS 8192
#define QSCALE 0.14433756729740643f
#define LOG2E 1.4426950408889634f

// ------------------- static scratch (no allocation allowed) -----------------
__device__ bf16  g_hb  [ROWS * D_];
__device__ bf16  g_act [ROWS * HID_];
__device__ bf16  g_q   [B_ * H_ * N_ * HD_];
__device__ bf16  g_k   [B_ * H_ * N_ * HD_];
__device__ bf16  g_vT  [B_ * H_ * 64 * N_];   // zero-init; pad rows 48..63 never written
__device__ bf16  g_E   [(size_t)B_ * N_ * N_ * H_];   // exp(premixed logits), (b,i,j,h)
__device__ float g_Zp  [B_ * N_ * H_ * 16];           // Z partials per j-block
__device__ bf16  g_o   [ROWS * D_];
__device__ float g_x1  [ROWS * D_];
__device__ bf16  g_wqkv [3 * D_ * D_];
__device__ bf16  g_wproj[D_ * D_];
__device__ bf16  g_wfc1 [HID_ * D_];
__device__ bf16  g_wfc2 [D_ * HID_];

// ------------------- fused fp32 -> bf16 convert for all 4 weights -----------
__global__ void cvt_all_kernel(const float* w0, bf16* o0, const float* w1, bf16* o1,
                               const float* w2, bf16* o2, const float* w3, bf16* o3)
{
    int i = blockIdx.x * 256 + threadIdx.x;            // float4 index
    const float* src;
    bf16* dst;
    int base;
    if (i < 110592)       { src = w0; dst = o0; base = i; }
    else if (i < 147456)  { src = w1; dst = o1; base = i - 110592; }
    else if (i < 294912)  { src = w2; dst = o2; base = i - 147456; }
    else if (i < 442368)  { src = w3; dst = o3; base = i - 294912; }
    else return;
    float4 v = reinterpret_cast<const float4*>(src)[base];
    reinterpret_cast<__nv_bfloat162*>(dst)[2 * base]     = __floats2bfloat162_rn(v.x, v.y);
    reinterpret_cast<__nv_bfloat162*>(dst)[2 * base + 1] = __floats2bfloat162_rn(v.z, v.w);
}

// ------------------- LayerNorm fp32 -> bf16 ---------------------------------
__global__ void ln_kernel(const float* __restrict__ x, const float* __restrict__ gw,
                          const float* __restrict__ bw, bf16* __restrict__ out)
{
    int row = blockIdx.x;
    int t   = threadIdx.x;
    const float* xr = x + (size_t)row * D_;
    float v0 = xr[t], v1 = xr[t + 128], v2 = xr[t + 256];
    float s  = v0 + v1 + v2;
    float ss = v0 * v0 + v1 * v1 + v2 * v2;
    for (int o = 16; o > 0; o >>= 1) {
        s  += __shfl_xor_sync(0xffffffffu, s,  o);
        ss += __shfl_xor_sync(0xffffffffu, ss, o);
    }
    __shared__ float rs[4];
    __shared__ float rq[4];
    if ((t & 31) == 0) { rs[t >> 5] = s; rq[t >> 5] = ss; }
    __syncthreads();
    s  = rs[0] + rs[1] + rs[2] + rs[3];
    ss = rq[0] + rq[1] + rq[2] + rq[3];
    float mean = s * (1.0f / 384.0f);
    float var  = ss * (1.0f / 384.0f) - mean * mean;
    float rstd = rsqrtf(var + 1e-5f);
    bf16* orow = out + (size_t)row * D_;
    orow[t]       = __float2bfloat16((v0 - mean) * rstd * gw[t]       + bw[t]);
    orow[t + 128] = __float2bfloat16((v1 - mean) * rstd * gw[t + 128] + bw[t + 128]);
    orow[t + 256] = __float2bfloat16((v2 - mean) * rstd * gw[t + 256] + bw[t + 256]);
}

// ------------------- PTX helpers --------------------------------------------
__device__ __forceinline__ void mma16816(float* c, const uint32_t* a, const uint32_t* b)
{
    asm volatile(
        "mma.sync.aligned.m16n8k16.row.col.f32.bf16.bf16.f32 "
        "{%0,%1,%2,%3}, {%4,%5,%6,%7}, {%8,%9}, {%0,%1,%2,%3};\n"
        : "+f"(c[0]), "+f"(c[1]), "+f"(c[2]), "+f"(c[3])
        : "r"(a[0]), "r"(a[1]), "r"(a[2]), "r"(a[3]), "r"(b[0]), "r"(b[1]));
}

__device__ __forceinline__ void ldsm_x4(uint32_t* r, uint32_t addr)
{
    asm volatile("ldmatrix.sync.aligned.m8n8.x4.shared.b16 {%0,%1,%2,%3}, [%4];\n"
                 : "=r"(r[0]), "=r"(r[1]), "=r"(r[2]), "=r"(r[3]) : "r"(addr));
}

__device__ __forceinline__ void cp_async16(uint32_t dst, const void* src)
{
    asm volatile("cp.async.cg.shared.global [%0], [%1], 16;\n" :: "r"(dst), "l"(src));
}
__device__ __forceinline__ void cp_commit()
{
    asm volatile("cp.async.commit_group;\n");
}
__device__ __forceinline__ void cp_wait0()
{
    asm volatile("cp.async.wait_group 0;\n" ::: "memory");
}
__device__ __forceinline__ void cp_wait1()
{
    asm volatile("cp.async.wait_group 1;\n" ::: "memory");
}

__device__ __forceinline__ float ex2f(float x)
{
    float y;
    asm("ex2.approx.f32 %0, %1;" : "=f"(y) : "f"(x));
    return y;
}
__device__ __forceinline__ float rcpf(float x)
{
    float y;
    asm("rcp.approx.f32 %0, %1;" : "=f"(y) : "f"(x));
    return y;
}
__device__ __forceinline__ uint32_t ex2_bf2(uint32_t x)
{
    uint32_t y;
    asm("ex2.approx.ftz.bf16x2 %0, %1;" : "=r"(y) : "r"(x));
    return y;
}

__device__ __forceinline__ uint32_t bf2_raw(__nv_bfloat162 v)
{
    return *reinterpret_cast<uint32_t*>(&v);
}
__device__ __forceinline__ __nv_bfloat162 raw_bf2(uint32_t v)
{
    return *reinterpret_cast<__nv_bfloat162*>(&v);
}

// ------------------- tensor-core GEMM  C = A @ B^T --------------------------
// 3-stage cp.async pipeline, 256 threads. MODE 0: qkv scatter; MODE 3: GELU;
// MODE 4: bias + residual + layerscale.
template<int BM, int BN, int MODE>
__global__ void __launch_bounds__(256)
gemm_kernel(const bf16* __restrict__ A, const bf16* __restrict__ Bw,
            int M, int N, int K, int lda, int ldb,
            const float* __restrict__ bias, const float* __restrict__ resid,
            const float* __restrict__ gamma, float* __restrict__ fout,
            bf16* __restrict__ bout, bf16* __restrict__ qo,
            bf16* __restrict__ ko, bf16* __restrict__ vo)
{
    constexpr int WM_CNT = BM / 32;
    constexpr int WN_TILE = BN * WM_CNT / 8;
    constexpr int NT = WN_TILE / 8;
    constexpr int A_STAGE = BM * 24;
    constexpr int B_STAGE = BN * 24;

    __shared__ bf16 As[3][BM][24];
    __shared__ bf16 Bs[3][BN][24];

    const int tid = threadIdx.x;
    const int w = tid >> 5;
    const int l = tid & 31;
    const int g = l >> 2;
    const int t = l & 3;
    const int wm = (w % WM_CNT) * 32;
    const int wn = (w / WM_CNT) * WN_TILE;
    const int m0 = blockIdx.y * BM;
    const int n0 = blockIdx.x * BN;

    const bf16* Ap = A;
    const bf16* Bp = Bw;

    const int arow = tid >> 1;
    const int acg  = (tid & 1) * 8;
    const int brow = tid >> 1;
    const int bcg  = (tid & 1) * 8;
    const bool doA = (tid < BM * 2);
    const bool doB = (tid < BN * 2);

    const bf16* aSrc = Ap + (size_t)(m0 + (doA ? arow : 0)) * lda + acg;
    const bf16* bSrc = Bp + (size_t)(n0 + (doB ? brow : 0)) * ldb + bcg;
    const uint32_t aDst0 = (uint32_t)__cvta_generic_to_shared(&As[0][doA ? arow : 0][acg]);
    const uint32_t bDst0 = (uint32_t)__cvta_generic_to_shared(&Bs[0][doB ? brow : 0][bcg]);

    float acc[2][NT][4];
    for (int mi = 0; mi < 2; mi++)
        for (int ni = 0; ni < NT; ni++)
            for (int e = 0; e < 4; e++)
                acc[mi][ni][e] = 0.0f;

    const int niter = K >> 4;

    if (doA) cp_async16(aDst0, aSrc);
    if (doB) cp_async16(bDst0, bSrc);
    cp_commit();
    if (niter > 1) {
        if (doA) cp_async16(aDst0 + A_STAGE * 2, aSrc + 16);
        if (doB) cp_async16(bDst0 + B_STAGE * 2, bSrc + 16);
    }
    cp_commit();

    int buf = 0;
    for (int it = 0; it < niter; it++) {
        cp_wait1();
        __syncthreads();
        {
            int pf = buf + 2; if (pf >= 3) pf -= 3;
            if (it + 2 < niter) {
                int kn = (it + 2) << 4;
                if (doA) cp_async16(aDst0 + (uint32_t)pf * (A_STAGE * 2), aSrc + kn);
                if (doB) cp_async16(bDst0 + (uint32_t)pf * (B_STAGE * 2), bSrc + kn);
            }
            cp_commit();
        }

        const bf16 (*Ab)[24] = As[buf];
        const bf16 (*Bb)[24] = Bs[buf];

        uint32_t af[2][4];
        for (int mi = 0; mi < 2; mi++) {
            int r = wm + mi * 16 + g;
            af[mi][0] = *reinterpret_cast<const uint32_t*>(&Ab[r][2 * t]);
            af[mi][1] = *reinterpret_cast<const uint32_t*>(&Ab[r + 8][2 * t]);
            af[mi][2] = *reinterpret_cast<const uint32_t*>(&Ab[r][2 * t + 8]);
            af[mi][3] = *reinterpret_cast<const uint32_t*>(&Ab[r + 8][2 * t + 8]);
        }
        uint32_t bfm[NT][2];
        for (int ni = 0; ni < NT; ni++) {
            int c = wn + ni * 8 + g;
            bfm[ni][0] = *reinterpret_cast<const uint32_t*>(&Bb[c][2 * t]);
            bfm[ni][1] = *reinterpret_cast<const uint32_t*>(&Bb[c][2 * t + 8]);
        }
        for (int mi = 0; mi < 2; mi++)
            for (int ni = 0; ni < NT; ni++)
                mma16816(acc[mi][ni], af[mi], bfm[ni]);

        buf++; if (buf == 3) buf = 0;
    }

    for (int mi = 0; mi < 2; mi++) {
        for (int ni = 0; ni < NT; ni++) {
            for (int hh = 0; hh < 2; hh++) {
                int row = m0 + wm + mi * 16 + g + hh * 8;
                int col = n0 + wn + ni * 8 + 2 * t;
                float v0 = acc[mi][ni][hh * 2 + 0];
                float v1 = acc[mi][ni][hh * 2 + 1];
                if (MODE == 0) {
                    int t3 = col / D_;
                    int r  = col - t3 * D_;
                    int hd = r / HD_;
                    int dd = r - hd * HD_;
                    int bb = row >> 10;
                    int ii = row & 1023;
                    size_t qk = ((size_t)(bb * H_ + hd) * N_ + ii) * HD_ + dd;
                    if (t3 == 0) {
                        __nv_bfloat162 p = __floats2bfloat162_rn(v0 * QSCALE, v1 * QSCALE);
                        *reinterpret_cast<__nv_bfloat162*>(&qo[qk]) = p;
                    } else if (t3 == 1) {
                        __nv_bfloat162 p = __floats2bfloat162_rn(v0, v1);
                        *reinterpret_cast<__nv_bfloat162*>(&ko[qk]) = p;
                    } else {
                        size_t vb = ((size_t)(bb * H_ + hd) * 64 + dd) * N_ + ii;
                        vo[vb]      = __float2bfloat16(v0);
                        vo[vb + N_] = __float2bfloat16(v1);
                    }
                } else if (MODE == 3) {
                    // GELU via sigmoid approximation: x * sigmoid(1.702 x)
                    float a0 = v0 + bias[col];
                    float a1 = v1 + bias[col + 1];
                    float s0 = rcpf(1.0f + ex2f(-1.702f * LOG2E * a0));
                    float s1 = rcpf(1.0f + ex2f(-1.702f * LOG2E * a1));
                    a0 *= s0;
                    a1 *= s1;
                    __nv_bfloat162 p = __floats2bfloat162_rn(a0, a1);
                    *reinterpret_cast<__nv_bfloat162*>(&bout[(size_t)row * N + col]) = p;
                } else {
                    float2 rr = *reinterpret_cast<const float2*>(&resid[(size_t)row * N + col]);
                    float2 o2;
                    o2.x = rr.x + gamma[col]     * (v0 + bias[col]);
                    o2.y = rr.y + gamma[col + 1] * (v1 + bias[col + 1]);
                    *reinterpret_cast<float2*>(&fout[(size_t)row * N + col]) = o2;
                }
            }
        }
    }
}

// ------------------- K1: QK^T (8 heads) + packed premix + exp + Z -----------
// grid (16 jb, 16 ib, 8 b); 256 threads; tile 64x64; dynamic smem 97056 B.
// Es layout: (row, h, j) at row*532 + h*66 + j  (bf16; packed bf16x2 pairs on j)
__global__ void __launch_bounds__(256)
score_mix_kernel(const bf16* __restrict__ q, const bf16* __restrict__ k,
                 const float* __restrict__ wl, const float* __restrict__ bl,
                 bf16* __restrict__ E, float* __restrict__ Zp)
{
    extern __shared__ char sm1[];
    bf16*  Qs  = reinterpret_cast<bf16*>(sm1);            // [2][64][56] 14336 B
    bf16*  Ks  = reinterpret_cast<bf16*>(sm1 + 14336);    // [2][64][56] 14336 B
    bf16*  Es  = reinterpret_cast<bf16*>(sm1 + 28672);    // [64][532]   68096 B
    __nv_bfloat162* wls2 = reinterpret_cast<__nv_bfloat162*>(sm1 + 96768);  // 64
    __nv_bfloat162* bls2 = reinterpret_cast<__nv_bfloat162*>(sm1 + 97024);  // 8

    const int tid = threadIdx.x;
    const int jb  = blockIdx.x;
    const int j0  = jb * 64;
    const int i0  = blockIdx.y * 64;
    const int b   = blockIdx.z;

    if (tid < 64) wls2[tid] = __float2bfloat162_rn(wl[tid] * LOG2E);
    if (tid < 8)  bls2[tid] = __float2bfloat162_rn(bl[tid] * LOG2E);

    const int w = tid >> 5, l = tid & 31, gq = l >> 2, t = l & 3;
    const int wm = (w & 3) * 16;          // M 64: 4 warp rows
    const int wn = (w >> 2) * 32;         // N 64: 2 warp cols of 32

    // ldmatrix lane addressing: tiles (m-lo,k-lo)(m-hi,k-lo)(m-lo,k-hi)(m-hi,k-hi)
    const int lr   = l & 7;
    const int sel  = l >> 3;              // 0..3
    const int rsel = (sel & 1) * 8;
    const int ksel = (sel >> 1) * 8;

    auto loadQK = [&](int h, int buf) {
        const bf16* qsrc = q + ((size_t)(b * H_ + h) * N_ + i0) * HD_;
        const bf16* ksrc = k + ((size_t)(b * H_ + h) * N_ + j0) * HD_;
        for (int idx = tid; idx < 384; idx += 256) {
            int r = idx / 6;
            int c = (idx - r * 6) * 8;
            cp_async16((uint32_t)__cvta_generic_to_shared(Qs + buf * 3584 + r * 56 + c),
                       qsrc + (size_t)r * HD_ + c);
            cp_async16((uint32_t)__cvta_generic_to_shared(Ks + buf * 3584 + r * 56 + c),
                       ksrc + (size_t)r * HD_ + c);
        }
    };

    const uint32_t qsBase = (uint32_t)__cvta_generic_to_shared(Qs);
    const uint32_t ksBase = (uint32_t)__cvta_generic_to_shared(Ks);
    // per-lane ldmatrix row bases (element offsets ×2 bytes)
    const uint32_t qRow  = ((uint32_t)(wm + rsel + lr) * 56 + ksel) * 2;
    const uint32_t kRow1 = ((uint32_t)(wn + rsel + lr) * 56 + ksel) * 2;
    const uint32_t kRow2 = kRow1 + 16 * 56 * 2;

    loadQK(0, 0);
    cp_commit();

    for (int h = 0; h < 8; h++) {
        cp_wait0();
        __syncthreads();
        if (h + 1 < 8) loadQK(h + 1, (h + 1) & 1);
        cp_commit();

        const uint32_t qb = qsBase + (h & 1) * 7168 + qRow;
        const uint32_t kb1 = ksBase + (h & 1) * 7168 + kRow1;
        const uint32_t kb2 = ksBase + (h & 1) * 7168 + kRow2;

        float acc[4][4];
        for (int nf = 0; nf < 4; nf++)
            for (int e = 0; e < 4; e++) acc[nf][e] = 0.0f;

#pragma unroll
        for (int k0 = 0; k0 < 48; k0 += 16) {
            uint32_t a[4], b1[4], b2[4];
            ldsm_x4(a,  qb  + k0 * 2);
            ldsm_x4(b1, kb1 + k0 * 2);
            ldsm_x4(b2, kb2 + k0 * 2);
            uint32_t bb[2];
            bb[0] = b1[0]; bb[1] = b1[2]; mma16816(acc[0], a, bb);
            bb[0] = b1[1]; bb[1] = b1[3]; mma16816(acc[1], a, bb);
            bb[0] = b2[0]; bb[1] = b2[2]; mma16816(acc[2], a, bb);
            bb[0] = b2[1]; bb[1] = b2[3]; mma16816(acc[3], a, bb);
        }
        // stage this head's scores as packed (j, j+1) bf16x2 into Es[row][h][col]
        for (int nf = 0; nf < 4; nf++) {
            for (int hh = 0; hh < 2; hh++) {
                int row = wm + gq + hh * 8;
                int col = wn + nf * 8 + 2 * t;
                __nv_bfloat162 pr = __floats2bfloat162_rn(acc[nf][hh * 2 + 0],
                                                          acc[nf][hh * 2 + 1]);
                *reinterpret_cast<__nv_bfloat162*>(&Es[row * 532 + h * 66 + col]) = pr;
            }
        }
    }
    __syncthreads();

    // packed premix + exp2 + E store + Z. thread: row mi, j-pairs 2*mj0 + 8p
    const int mi  = tid >> 2;
    const int mj0 = tid & 3;
    __nv_bfloat162 zacc2[8];
    for (int gg = 0; gg < 8; gg++) zacc2[gg] = __float2bfloat162_rn(0.0f);

    uint4* Eg = reinterpret_cast<uint4*>(E);
    for (int p = 0; p < 8; p++) {
        int j = 2 * mj0 + 8 * p;
        uint32_t s2[8];
#pragma unroll
        for (int hh = 0; hh < 8; hh++)
            s2[hh] = *reinterpret_cast<const uint32_t*>(&Es[mi * 532 + hh * 66 + j]);
        uint32_t e2[8];
#pragma unroll
        for (int gg = 0; gg < 8; gg++) {
            __nv_bfloat162 m = bls2[gg];
#pragma unroll
            for (int hh = 0; hh < 8; hh++)
                m = __hfma2(wls2[gg * 8 + hh], raw_bf2(s2[hh]), m);
            uint32_t ev = ex2_bf2(bf2_raw(m));
            e2[gg] = ev;
            zacc2[gg] = __hadd2(zacc2[gg], raw_bf2(ev));
        }
        uint32_t lo[4], hi[4];
#pragma unroll
        for (int kk = 0; kk < 4; kk++) {
            lo[kk] = __byte_perm(e2[2 * kk], e2[2 * kk + 1], 0x5410);
            hi[kk] = __byte_perm(e2[2 * kk], e2[2 * kk + 1], 0x7632);
        }
        size_t base = (size_t)(b * N_ + i0 + mi) * N_ + j0 + j;
        Eg[base]     = make_uint4(lo[0], lo[1], lo[2], lo[3]);
        Eg[base + 1] = make_uint4(hi[0], hi[1], hi[2], hi[3]);
    }
    // Z: convert packed accumulators, reduce over the 4 lanes sharing a row
    float zf[8];
#pragma unroll
    for (int gg = 0; gg < 8; gg++) {
        float2 f = __bfloat1622float2(zacc2[gg]);
        zf[gg] = f.x + f.y;
        zf[gg] += __shfl_xor_sync(0xffffffffu, zf[gg], 1);
        zf[gg] += __shfl_xor_sync(0xffffffffu, zf[gg], 2);
    }
    if ((tid & 3) == 0) {
        float* zp = Zp + (size_t)(b * N_ + i0 + mi) * 128 + jb;
#pragma unroll
        for (int gg = 0; gg < 8; gg++) zp[gg * 16] = zf[gg];
    }
}

// ------------------- K2: normalize + packed postmix + AV --------------------
// grid (32 i-blocks, 8 b); 256 threads; dynamic smem 111904 B.
__global__ void __launch_bounds__(256, 2)
attn_pv_kernel(const bf16* __restrict__ E, const float* __restrict__ Zp,
               const bf16* __restrict__ vT, const float* __restrict__ ww,
               const float* __restrict__ bw, bf16* __restrict__ o)
{
    extern __shared__ char sm2[];
    bf16*  Vs   = reinterpret_cast<bf16*>(sm2);             // [8][64][72]
    bf16*  Pb   = reinterpret_cast<bf16*>(sm2 + 73728);     // [8][32][72]
    float* invZ = reinterpret_cast<float*>(sm2 + 110592);   // [32][8]
    __nv_bfloat162* wws2 = reinterpret_cast<__nv_bfloat162*>(sm2 + 111616);  // 64
    __nv_bfloat162* bws2 = reinterpret_cast<__nv_bfloat162*>(sm2 + 111872);  // 8

    const int tid = threadIdx.x;
    const int i0  = blockIdx.x * 32;
    const int b   = blockIdx.y;
    const int w = tid >> 5, l = tid & 31, gq = l >> 2, t = l & 3;
    const int wm = (w & 1) * 16;          // M 32
    const int wn = (w >> 1) * 16;         // N 64 padded (warps with wn=48 idle in mma)

    const int lr   = l & 7;
    const int sel  = l >> 3;
    const int rsel = (sel & 1) * 8;
    const int ksel = (sel >> 1) * 8;

    if (tid < 64) wws2[tid] = __float2bfloat162_rn(ww[tid]);
    if (tid < 8)  bws2[tid] = __float2bfloat162_rn(bw[tid]);
    {
        int i = tid >> 3, gg = tid & 7;
        const float* zp = Zp + (size_t)(b * N_ + i0 + i) * 128 + gg * 16;
        float s = 0.0f;
        for (int qq = 0; qq < 16; qq++) s += zp[qq];
        invZ[i * 8 + gg] = 1.0f / s;
    }
    __syncthreads();

    float acc[8][2][4];
    for (int gg = 0; gg < 8; gg++)
        for (int nf = 0; nf < 2; nf++)
            for (int e = 0; e < 4; e++) acc[gg][nf][e] = 0.0f;

    const int ei  = tid >> 3;     // row 0..31
    const int ej0 = tid & 7;
    const uint4* Eg = reinterpret_cast<const uint4*>(E);

    __nv_bfloat162 izr2[8];
    for (int hh = 0; hh < 8; hh++)
        izr2[hh] = __float2bfloat162_rn(invZ[ei * 8 + hh]);

    // per-lane ldmatrix row bases (byte offsets into Pb / Vs)
    const uint32_t pbBase = (uint32_t)__cvta_generic_to_shared(Pb)
                          + ((uint32_t)(wm + rsel + lr) * 72 + ksel) * 2;
    const uint32_t vsBase = (uint32_t)__cvta_generic_to_shared(Vs)
                          + ((uint32_t)(wn + rsel + lr) * 72 + ksel) * 2;

    for (int jblk = 0; jblk < 16; jblk++) {
        const int j0 = jblk * 64;
        uint4 evA[4], evB[4];
        size_t ebase = (size_t)(b * N_ + i0 + ei) * N_ + j0;
#pragma unroll
        for (int p = 0; p < 4; p++) {
            evA[p] = Eg[ebase + 2 * ej0 + 16 * p];
            evB[p] = Eg[ebase + 2 * ej0 + 16 * p + 1];
        }
        __syncthreads();    // previous mma done; smem reusable
        for (int idx = tid; idx < 4096; idx += 256) {
            int gg = idx >> 9;
            int r  = (idx >> 3) & 63;
            int c  = (idx & 7) * 8;
            *reinterpret_cast<uint4*>(Vs + (gg * 64 + r) * 72 + c) =
                *reinterpret_cast<const uint4*>(vT + ((size_t)(b * H_ + gg) * 64 + r) * N_ + j0 + c);
        }
#pragma unroll
        for (int half = 0; half < 2; half++) {
            __nv_bfloat162 ph2[2][8];
#pragma unroll
            for (int pp = 0; pp < 2; pp++) {
                int pi = half * 2 + pp;
                const uint32_t* Aw = reinterpret_cast<const uint32_t*>(&evA[pi]);
                const uint32_t* Bw = reinterpret_cast<const uint32_t*>(&evB[pi]);
#pragma unroll
                for (int kk = 0; kk < 4; kk++) {
                    uint32_t slo = __byte_perm(Aw[kk], Bw[kk], 0x5410);
                    uint32_t shi = __byte_perm(Aw[kk], Bw[kk], 0x7632);
                    ph2[pp][2 * kk]     = __hmul2(raw_bf2(slo), izr2[2 * kk]);
                    ph2[pp][2 * kk + 1] = __hmul2(raw_bf2(shi), izr2[2 * kk + 1]);
                }
            }
#pragma unroll
            for (int gg = 0; gg < 8; gg++) {
                __nv_bfloat162 pv0 = bws2[gg];
                __nv_bfloat162 pv1 = bws2[gg];
#pragma unroll
                for (int hh = 0; hh < 8; hh++) {
                    __nv_bfloat162 wv = wws2[gg * 8 + hh];
                    pv0 = __hfma2(wv, ph2[0][hh], pv0);
                    pv1 = __hfma2(wv, ph2[1][hh], pv1);
                }
                int j1 = 2 * ej0 + 16 * (half * 2 + 0);
                int j2 = 2 * ej0 + 16 * (half * 2 + 1);
                *reinterpret_cast<__nv_bfloat162*>(&Pb[(gg * 32 + ei) * 72 + j1]) = pv0;
                *reinterpret_cast<__nv_bfloat162*>(&Pb[(gg * 32 + ei) * 72 + j2]) = pv1;
            }
        }
        __syncthreads();
        if (wn < 48) {
            for (int gg = 0; gg < 8; gg++) {
                const uint32_t pA = pbBase + (uint32_t)gg * (32 * 72 * 2);
                const uint32_t pV = vsBase + (uint32_t)gg * (64 * 72 * 2);
#pragma unroll
                for (int k0 = 0; k0 < 64; k0 += 16) {
                    uint32_t a[4], bv[4];
                    ldsm_x4(a,  pA + k0 * 2);
                    ldsm_x4(bv, pV + k0 * 2);
                    uint32_t bb[2];
                    bb[0] = bv[0]; bb[1] = bv[2]; mma16816(acc[gg][0], a, bb);
                    bb[0] = bv[1]; bb[1] = bv[3]; mma16816(acc[gg][1], a, bb);
                }
            }
        }
    }

    if (wn < 48) {
        for (int gg = 0; gg < 8; gg++) {
            for (int nf = 0; nf < 2; nf++) {
                for (int hh = 0; hh < 2; hh++) {
                    int row = wm + gq + hh * 8;
                    int col = wn + nf * 8 + 2 * t;
                    if (col < HD_) {
                        __nv_bfloat162 p = __floats2bfloat162_rn(acc[gg][nf][hh * 2 + 0],
                                                                 acc[gg][nf][hh * 2 + 1]);
                        *reinterpret_cast<__nv_bfloat162*>(
                            &o[(size_t)(b * N_ + i0 + row) * D_ + gg * HD_ + col]) = p;
                    }
                }
            }
        }
    }
}

// ------------------- host launcher ------------------------------------------
extern "C" void kernel_launch(void* const* d_in, const int* in_sizes, int n_in,
                              void* d_out, int out_size)
{
    (void)in_sizes; (void)n_in; (void)out_size;
    const float* x      = (const float*)d_in[0];
    const float* ln1_g  = (const float*)d_in[1];
    const float* ln1_b  = (const float*)d_in[2];
    const float* w_qkv  = (const float*)d_in[3];
    const float* w_proj = (const float*)d_in[4];
    const float* b_proj = (const float*)d_in[5];
    const float* w_l    = (const float*)d_in[6];
    const float* b_l    = (const float*)d_in[7];
    const float* w_w    = (const float*)d_in[8];
    const float* b_w    = (const float*)d_in[9];
    const float* ln2_g  = (const float*)d_in[10];
    const float* ln2_b  = (const float*)d_in[11];
    const float* w_fc1  = (const float*)d_in[12];
    const float* b_fc1  = (const float*)d_in[13];
    const float* w_fc2  = (const float*)d_in[14];
    const float* b_fc2  = (const float*)d_in[15];
    const float* gamma1 = (const float*)d_in[16];
    const float* gamma2 = (const float*)d_in[17];
    float* out = (float*)d_out;

    bf16 *hb, *act, *qb, *kb, *vT, *E, *o, *wqkvb, *wprojb, *wfc1b, *wfc2b;
    float *x1, *Zp;
    cudaGetSymbolAddress((void**)&hb,     g_hb);
    cudaGetSymbolAddress((void**)&act,    g_act);
    cudaGetSymbolAddress((void**)&qb,     g_q);
    cudaGetSymbolAddress((void**)&kb,     g_k);
    cudaGetSymbolAddress((void**)&vT,     g_vT);
    cudaGetSymbolAddress((void**)&E,      g_E);
    cudaGetSymbolAddress((void**)&Zp,     g_Zp);
    cudaGetSymbolAddress((void**)&o,      g_o);
    cudaGetSymbolAddress((void**)&x1,     g_x1);
    cudaGetSymbolAddress((void**)&wqkvb,  g_wqkv);
    cudaGetSymbolAddress((void**)&wprojb, g_wproj);
    cudaGetSymbolAddress((void**)&wfc1b,  g_wfc1);
    cudaGetSymbolAddress((void**)&wfc2b,  g_wfc2);

    cudaFuncSetAttribute(score_mix_kernel, cudaFuncAttributeMaxDynamicSharedMemorySize, 97056);
    cudaFuncSetAttribute(attn_pv_kernel,   cudaFuncAttributeMaxDynamicSharedMemorySize, 111904);

    cvt_all_kernel<<<1728, 256>>>(w_qkv, wqkvb, w_proj, wprojb,
                                  w_fc1, wfc1b, w_fc2, wfc2b);

    ln_kernel<<<ROWS, 128>>>(x, ln1_g, ln1_b, hb);

    gemm_kernel<128, 128, 0><<<dim3(9, 64, 1), 256>>>(
        hb, wqkvb, ROWS, 1152, 384, 384, 384,
        nullptr, nullptr, nullptr, nullptr, nullptr, qb, kb, vT);

    score_mix_kernel<<<dim3(16, 16, 8), 256, 97056>>>(qb, kb, w_l, b_l, E, Zp);

    attn_pv_kernel<<<dim3(32, 8), 256, 111904>>>(E, Zp, vT, w_w, b_w, o);

    gemm_kernel<64, 128, 4><<<dim3(3, 128, 1), 256>>>(
        o, wprojb, ROWS, D_, D_, D_, D_,
        b_proj, x, gamma1, x1, nullptr, nullptr, nullptr, nullptr);

    ln_kernel<<<ROWS, 128>>>(x1, ln2_g, ln2_b, hb);

    gemm_kernel<128, 128, 3><<<dim3(12, 64, 1), 256>>>(
        hb, wfc1b, ROWS, HID_, D_, D_, D_,
        b_fc1, nullptr, nullptr, nullptr, act, nullptr, nullptr, nullptr);

    gemm_kernel<64, 128, 4><<<dim3(3, 128, 1), 256>>>(
        act, wfc2b, ROWS, D_, HID_, HID_, HID_,
        b_fc2, x1, gamma2, out, nullptr, nullptr, nullptr, nullptr);
}